// round 15
// baseline (speedup 1.0000x reference)
#include <cuda_runtime.h>
#include <cuda_bf16.h>
#include <math.h>
#include <stdint.h>

#define B_    16384
#define F_    64
#define H_    512
#define C_    512
#define NBINS 30
#define MULT_ 91
#define MP_   96
#define NOUTP (F_*MP_)     // 6144
#define KIN   (F_+C_)      // 576
#define NBLK  3
#define HH    (H_*H_)

// ---------------- device scratch ----------------
__device__ __nv_bfloat16 g_A[B_*KIN];
__device__ __nv_bfloat16 g_X[B_*H_];
__device__ __nv_bfloat16 g_Y[B_*H_];
__device__ float g_t [B_*H_];
__device__ float g_sg[(size_t)B_*NBLK*H_];          // all 3 gates, row stride 1536
__device__ float g_CDF[(size_t)B_*F_];              // per-(b,f) spline CDF
__device__ float g_pb[10*H_];                       // permuted biases
__device__ __nv_bfloat16 g_Wcat[H_*KIN];
__device__ __nv_bfloat16 g_Whh[2*NBLK*HH];
__device__ __nv_bfloat16 g_Wcb[NBLK*HH];
__device__ __nv_bfloat16 g_Wout[(size_t)NOUTP*H_];

// ---------------- degree-sort permutation (MADE degrees d(j)=j%63+1) ----------------
__host__ __device__ __forceinline__ int deg_s(int s)  { return (s < 72) ? s / 9 + 1 : s / 8; }
__host__ __device__ __forceinline__ int cum_d(int d)  { return 8 * d + (d < 8 ? d : 8); }
__host__ __device__ __forceinline__ int perm_s(int s) {
    int d = deg_s(s);
    int r = (s < 72) ? s % 9 : (s & 7);
    return (d - 1) + 63 * r;
}

// ---------------- helpers ----------------
__device__ __forceinline__ uint32_t smem_u32(const void* p) {
    uint32_t a;
    asm("{ .reg .u64 t; cvta.to.shared.u64 t, %1; cvt.u32.u64 %0, t; }" : "=r"(a) : "l"(p));
    return a;
}
__device__ __forceinline__ void cp16(uint32_t dst, const void* src) {
    asm volatile("cp.async.cg.shared.global [%0], [%1], 16;" :: "r"(dst), "l"(src));
}
#define CP_COMMIT() asm volatile("cp.async.commit_group;" ::: "memory")
#define CP_WAIT(n)  asm volatile("cp.async.wait_group %0;" :: "n"(n) : "memory")

__device__ __forceinline__ void ldsm4(uint32_t& r0, uint32_t& r1, uint32_t& r2, uint32_t& r3,
                                      uint32_t addr) {
    asm volatile("ldmatrix.sync.aligned.m8n8.x4.shared.b16 {%0,%1,%2,%3}, [%4];"
                 : "=r"(r0), "=r"(r1), "=r"(r2), "=r"(r3) : "r"(addr));
}
__device__ __forceinline__ void mma16816(float* c, const uint32_t* a, const uint32_t* b) {
    asm volatile(
        "mma.sync.aligned.m16n8k16.row.col.f32.bf16.bf16.f32 "
        "{%0,%1,%2,%3}, {%4,%5,%6,%7}, {%8,%9}, {%0,%1,%2,%3};"
        : "+f"(c[0]), "+f"(c[1]), "+f"(c[2]), "+f"(c[3])
        : "r"(a[0]), "r"(a[1]), "r"(a[2]), "r"(a[3]), "r"(b[0]), "r"(b[1]));
}
__device__ __forceinline__ float softplusf(float x) {
    return fmaxf(x, 0.f) + log1pf(expf(-fabsf(x)));
}

// RQ spline for one (row, feature): pp = raw GEMM outputs (96 floats), bo = b_out slice
__device__ __forceinline__ float spline_eval(const float* __restrict__ pp,
                                             const float* __restrict__ bo, float x) {
    if (x == 1.0f) return 1.0f;
    const float scale = 0.04419417382415922f;  // 1/sqrt(512)
    float ew[NBINS], mx = -1e30f;
    #pragma unroll
    for (int k = 0; k < NBINS; k++) { ew[k] = (pp[k] + bo[k]) * scale; mx = fmaxf(mx, ew[k]); }
    float s = 0.f;
    #pragma unroll
    for (int k = 0; k < NBINS; k++) { ew[k] = expf(ew[k] - mx); s += ew[k]; }
    float inv = (1.f - 1e-3f * NBINS) / s;
    float cw[NBINS + 1];
    cw[0] = 0.f;
    float run = 0.f;
    #pragma unroll
    for (int k = 0; k < NBINS; k++) { run += 1e-3f + ew[k] * inv; cw[k + 1] = run; }
    cw[NBINS] = 1.f;

    float eh[NBINS];
    mx = -1e30f;
    #pragma unroll
    for (int k = 0; k < NBINS; k++) { eh[k] = (pp[NBINS + k] + bo[NBINS + k]) * scale; mx = fmaxf(mx, eh[k]); }
    s = 0.f;
    #pragma unroll
    for (int k = 0; k < NBINS; k++) { eh[k] = expf(eh[k] - mx); s += eh[k]; }
    inv = (1.f - 1e-3f * NBINS) / s;
    float ch[NBINS + 1];
    ch[0] = 0.f;
    run = 0.f;
    #pragma unroll
    for (int k = 0; k < NBINS; k++) { run += 1e-3f + eh[k] * inv; ch[k + 1] = run; }
    ch[NBINS] = 1.f;

    int cnt = 0;
    #pragma unroll
    for (int k = 0; k <= NBINS; k++) {
        float loc = (k == NBINS) ? (1.f + 1e-6f) : cw[k];
        cnt += (x >= loc) ? 1 : 0;
    }
    int idx = min(max(cnt - 1, 0), NBINS - 1);

    float in_cw = cw[idx], in_w = cw[idx + 1] - cw[idx];
    float in_ch = ch[idx], in_h = ch[idx + 1] - ch[idx];
    float d0 = 1e-3f + softplusf(pp[2 * NBINS + idx]     + bo[2 * NBINS + idx]);
    float d1 = 1e-3f + softplusf(pp[2 * NBINS + idx + 1] + bo[2 * NBINS + idx + 1]);

    float delta = in_h / in_w;
    float theta = (x - in_cw) / in_w;
    float tt = theta * (1.f - theta);
    float num = in_h * (delta * theta * theta + d0 * tt);
    float den = delta + (d0 + d1 - 2.f * delta) * tt;
    return in_ch + num / den;
}

// ---------------- prep kernels (mask + permute + transpose; all bf16) ----------------
__global__ void prepA(const float* __restrict__ pred, const float* __restrict__ ctx) {
    int i = blockIdx.x * blockDim.x + threadIdx.x;
    if (i >= B_*KIN) return;
    int r = i / KIN, c = i % KIN;
    float v = (c < F_) ? pred[r*F_ + c] : ctx[r*C_ + (c - F_)];
    g_A[i] = __float2bfloat16(v);
}
__global__ void prepWcat(const float* __restrict__ W_in, const float* __restrict__ Wc_in) {
    int i = blockIdx.x * blockDim.x + threadIdx.x;
    if (i >= H_*KIN) return;
    int n = i / KIN, k = i % KIN;
    int no = perm_s(n), dn = deg_s(n);
    float v;
    if (k < F_) { v = (dn >= k + 1) ? W_in[k*H_ + no] : 0.f; }
    else        { v = Wc_in[(k - F_)*H_ + no]; }
    g_Wcat[i] = __float2bfloat16(v);
}
__global__ void prepWhh(const float* __restrict__ Wb1, const float* __restrict__ Wb2) {
    int i = blockIdx.x * blockDim.x + threadIdx.x;
    if (i >= 2*NBLK*HH) return;
    int mat = i / HH, rem = i % HH;
    int n = rem / H_, k = rem % H_;
    const float* W = (mat < NBLK) ? (Wb1 + (size_t)mat*HH) : (Wb2 + (size_t)(mat - NBLK)*HH);
    float v = (deg_s(k) <= deg_s(n)) ? W[perm_s(k)*H_ + perm_s(n)] : 0.f;
    g_Whh[i] = __float2bfloat16(v);
}
__global__ void prepWcb(const float* __restrict__ Wcb) {
    int i = blockIdx.x * blockDim.x + threadIdx.x;
    if (i >= NBLK*HH) return;
    int mat = i / HH, rem = i % HH;
    int n = rem / H_, k = rem % H_;
    g_Wcb[i] = __float2bfloat16(Wcb[(size_t)mat*HH + k*H_ + perm_s(n)]);
}
__global__ void prepWout(const float* __restrict__ W_out) {
    size_t i = (size_t)blockIdx.x * blockDim.x + threadIdx.x;
    if (i >= (size_t)NOUTP*H_) return;
    int n = (int)(i / H_), k = (int)(i % H_);
    int f = n / MP_, j = n % MP_;
    float v = 0.f;
    if (j < MULT_ && f >= deg_s(k)) v = W_out[(size_t)perm_s(k)*(F_*MULT_) + f*MULT_ + j];
    g_Wout[i] = __float2bfloat16(v);
}
__global__ void permB(const float* __restrict__ b_in, const float* __restrict__ bc_in,
                      const float* __restrict__ bb1, const float* __restrict__ bb2,
                      const float* __restrict__ bcb) {
    int i = blockIdx.x * blockDim.x + threadIdx.x;
    if (i >= 10*H_) return;
    int v = i / H_, s = i % H_, j = perm_s(s);
    float x;
    if      (v == 0) x = b_in[j] + bc_in[j];
    else if (v <= 3) x = bb1[(v-1)*H_ + j];
    else if (v <= 6) x = bb2[(v-4)*H_ + j];
    else             x = bcb[(v-7)*H_ + j];
    g_pb[i] = x;
}

// ---------------- pure-bf16 mma.sync GEMM, 2 CTAs/SM, fused epilogues ----------------
// EPI: 0=t-init  1=relu  2=sigmoid  3=GLU residual  5=spline
// KMODE: 0=full K  1=HH (N=sorted hidden)  2=out (N=2 features/tile, BN=192)
#define BK 32
#define NSTAGE 3
#define ROWB 80

template<int BMv, int BNv>
__device__ __forceinline__ void issue_stage_t(
    uint32_t sb, const __nv_bfloat16* A, int lda,
    const __nv_bfloat16* Bh, int K,
    int m0, int n0, int k0, int tid)
{
    constexpr int A_B = BMv * ROWB;
    constexpr int NCP = (BMv + BNv) * 4;
    #pragma unroll
    for (int it = 0; it < NCP/256; it++) {
        int i = tid + it * 256;
        if (i < BMv*4) {
            int r = i >> 2, c = i & 3;
            cp16(sb + r*ROWB + c*16, A + (size_t)(m0 + r) * lda + k0 + c*8);
        } else {
            int j = i - BMv*4;
            int r = j >> 2, c = j & 3;
            cp16(sb + A_B + r*ROWB + c*16, Bh + (size_t)(n0 + r) * K + k0 + c*8);
        }
    }
}

template<int EPI, bool RELUF, int KMODE, int BMv, int BNv>
__global__ void __launch_bounds__(256, 2) gemm_bf1(
    const __nv_bfloat16* __restrict__ A, int lda,
    const __nv_bfloat16* __restrict__ Bh, int K,
    const float* __restrict__ bias1, int sg_ld,
    float* __restrict__ tbuf, float* __restrict__ sgbuf,
    const float* __restrict__ pred, float* __restrict__ cdf,
    __nv_bfloat16* __restrict__ outX)
{
    constexpr int WR  = BMv / 64;
    constexpr int WC  = 8 / WR;
    constexpr int WNW = BNv / WC;
    constexpr int NT  = WNW / 8;
    constexpr int A_B = BMv * ROWB;
    constexpr int B_B = BNv * ROWB;
    constexpr int STG = A_B + B_B;

    extern __shared__ char smem[];
    uint32_t sbase = smem_u32(smem);
    int tid = threadIdx.x;
    int lane = tid & 31, wid = tid >> 5;
    int wm = (wid / WC) * 64;
    int wn = (wid % WC) * WNW;
    int m0 = blockIdx.y * BMv, n0 = blockIdx.x * BNv;

    // degree-limited K (skipped rows are exact zeros in sorted weights)
    int klim = K;
    if (KMODE == 1) {
        int dmax = deg_s(n0 + BNv - 1);
        klim = min(K, (cum_d(dmax) + BK - 1) & ~(BK - 1));
    } else if (KMODE == 2) {
        int T = 2 * blockIdx.x + 1;
        if (T > 63) T = 63;
        klim = min(K, (cum_d(T) + BK - 1) & ~(BK - 1));
    }
    const int kiters = klim / BK;

    float acc[4][NT][4];
    #pragma unroll
    for (int mt = 0; mt < 4; mt++)
        #pragma unroll
        for (int nt = 0; nt < NT; nt++)
            #pragma unroll
            for (int q = 0; q < 4; q++) acc[mt][nt][q] = 0.f;

    #pragma unroll
    for (int s = 0; s < NSTAGE - 1; s++) {
        if (s < kiters)
            issue_stage_t<BMv,BNv>(sbase + s*STG, A, lda, Bh, K, m0, n0, s*BK, tid);
        CP_COMMIT();
    }

    int a_row = (lane & 15);
    uint32_t a_colb = (lane >> 4) * 16;
    int b_row = ((lane >> 4) << 3) + (lane & 7);
    uint32_t b_colb = ((lane >> 3) & 1) * 16;

    for (int ki = 0; ki < kiters; ki++) {
        CP_WAIT(NSTAGE - 2);
        __syncthreads();

        int kn = ki + NSTAGE - 1;
        if (kn < kiters)
            issue_stage_t<BMv,BNv>(sbase + (kn % NSTAGE)*STG, A, lda, Bh, K,
                                   m0, n0, kn*BK, tid);
        CP_COMMIT();

        uint32_t sb = sbase + (ki % NSTAGE) * STG;
        #pragma unroll
        for (int ks = 0; ks < 2; ks++) {
            uint32_t kb = ks * 32;
            uint32_t ah[4][4];
            #pragma unroll
            for (int mt = 0; mt < 4; mt++) {
                uint32_t ar = (uint32_t)(wm + mt*16 + a_row) * ROWB + kb + a_colb;
                ldsm4(ah[mt][0], ah[mt][1], ah[mt][2], ah[mt][3], sb + ar);
            }
            uint32_t bh[NT][2];
            #pragma unroll
            for (int bt = 0; bt < NT/2; bt++) {
                uint32_t br = (uint32_t)(wn + bt*16 + b_row) * ROWB + kb + b_colb;
                ldsm4(bh[2*bt][0], bh[2*bt][1], bh[2*bt+1][0], bh[2*bt+1][1], sb + A_B + br);
            }
            #pragma unroll
            for (int mt = 0; mt < 4; mt++)
                #pragma unroll
                for (int nt = 0; nt < NT; nt++)
                    mma16816(acc[mt][nt], ah[mt], bh[nt]);
        }
        __syncthreads();
    }

    if (EPI == 5) {
        // ---- fused spline epilogue, TWO PASSES of 64 rows each so the
        // transpose tile (64 x 194 f32 = 49.7 KB) fits the 3-stage pipeline
        // footprint (76.8 KB) and the kernel runs 2 CTAs/SM ----
        constexpr int LDD = 194;
        float* Dsm = reinterpret_cast<float*>(smem);
        #pragma unroll
        for (int h = 0; h < 2; h++) {
            __syncthreads();
            if (wm == h * 64) {
                #pragma unroll
                for (int mt = 0; mt < 4; mt++)
                    #pragma unroll
                    for (int nt = 0; nt < NT; nt++) {
                        int rl = mt*16 + (lane >> 2);
                        int cl = wn + nt*8 + (lane & 3) * 2;
                        *reinterpret_cast<float2*>(&Dsm[rl*LDD + cl])     = make_float2(acc[mt][nt][0], acc[mt][nt][1]);
                        *reinterpret_cast<float2*>(&Dsm[(rl+8)*LDD + cl]) = make_float2(acc[mt][nt][2], acc[mt][nt][3]);
                    }
            }
            __syncthreads();
            if (tid < 128) {
                int row = tid >> 1, feat = tid & 1;
                int gf = 2 * blockIdx.x + feat;
                int gr = m0 + h * 64 + row;
                float x = pred[gr * F_ + gf];
                float cdfv = spline_eval(Dsm + row * LDD + feat * MP_,
                                         bias1 + gf * MULT_, x);
                cdf[gr * F_ + gf] = cdfv;
            }
        }
        return;
    }

    // ---- standard epilogues ----
    #pragma unroll
    for (int mt = 0; mt < 4; mt++)
        #pragma unroll
        for (int nt = 0; nt < NT; nt++) {
            #pragma unroll
            for (int half = 0; half < 2; half++) {
                float v0 = acc[mt][nt][half*2], v1 = acc[mt][nt][half*2+1];
                int gr = m0 + wm + mt*16 + (lane >> 2) + half*8;
                int gc = n0 + wn + nt*8 + (lane & 3) * 2;
                if (EPI == 0) {
                    v0 += bias1[gc]; v1 += bias1[gc+1];
                    int g = gr * H_ + gc;
                    *reinterpret_cast<float2*>(&tbuf[g]) = make_float2(v0, v1);
                    __nv_bfloat162 hv;
                    hv.x = __float2bfloat16(fmaxf(v0, 0.f));
                    hv.y = __float2bfloat16(fmaxf(v1, 0.f));
                    *reinterpret_cast<__nv_bfloat162*>(&outX[g]) = hv;
                } else if (EPI == 1) {
                    v0 += bias1[gc]; v1 += bias1[gc+1];
                    int g = gr * H_ + gc;
                    __nv_bfloat162 hv;
                    hv.x = __float2bfloat16(fmaxf(v0, 0.f));
                    hv.y = __float2bfloat16(fmaxf(v1, 0.f));
                    *reinterpret_cast<__nv_bfloat162*>(&outX[g]) = hv;
                } else if (EPI == 2) {
                    v0 += bias1[gc]; v1 += bias1[gc+1];
                    float s0 = 1.f / (1.f + expf(-v0)), s1 = 1.f / (1.f + expf(-v1));
                    *reinterpret_cast<float2*>(&sgbuf[(size_t)gr * sg_ld + gc]) = make_float2(s0, s1);
                } else if (EPI == 3) {
                    v0 += bias1[gc]; v1 += bias1[gc+1];
                    int g = gr * H_ + gc;
                    float2 tv = *reinterpret_cast<const float2*>(&tbuf[g]);
                    float2 sv = *reinterpret_cast<const float2*>(&sgbuf[(size_t)gr * sg_ld + gc]);
                    float t0 = tv.x + v0 * sv.x, t1 = tv.y + v1 * sv.y;
                    *reinterpret_cast<float2*>(&tbuf[g]) = make_float2(t0, t1);
                    float z0 = RELUF ? fmaxf(t0, 0.f) : t0;
                    float z1 = RELUF ? fmaxf(t1, 0.f) : t1;
                    __nv_bfloat162 hv;
                    hv.x = __float2bfloat16(z0);
                    hv.y = __float2bfloat16(z1);
                    *reinterpret_cast<__nv_bfloat162*>(&outX[g]) = hv;
                }
            }
        }
}

// ---------------- product over features (same double shfl-tree order) ----------------
__global__ void prod_kernel(const float* __restrict__ cdf, float* __restrict__ out) {
    int tid = threadIdx.x;
    int r = tid >> 6, f = tid & 63;
    int b = blockIdx.x * 4 + r;
    double vv = (double)cdf[(size_t)b * F_ + f];
    #pragma unroll
    for (int o = 16; o > 0; o >>= 1)
        vv *= __shfl_xor_sync(0xffffffffu, vv, o);
    __shared__ double sred[8];
    int w = tid >> 5;
    if ((tid & 31) == 0) sred[w] = vv;
    __syncthreads();
    if (f == 0) out[b] = (float)(sred[2*r] * sred[2*r + 1]);
}

// ---------------- launch ----------------
extern "C" void kernel_launch(void* const* d_in, const int* in_sizes, int n_in,
                              void* d_out, int out_size) {
    const float* pred  = (const float*)d_in[0];
    const float* ctx   = (const float*)d_in[1];
    const float* W_in  = (const float*)d_in[2];
    const float* b_in  = (const float*)d_in[3];
    const float* Wc_in = (const float*)d_in[4];
    const float* bc_in = (const float*)d_in[5];
    const float* Wb1   = (const float*)d_in[6];
    const float* bb1   = (const float*)d_in[7];
    const float* Wb2   = (const float*)d_in[8];
    const float* bb2   = (const float*)d_in[9];
    const float* Wcb   = (const float*)d_in[10];
    const float* bcb   = (const float*)d_in[11];
    const float* W_out = (const float*)d_in[12];
    const float* b_out = (const float*)d_in[13];
    float* out = (float*)d_out;

    // per-instantiation dynamic smem: 3 stages of (BM + BN)*80
    const int SM_128_128 = NSTAGE * (128 + 128) * ROWB;   // 61440
    const int SM_128_256 = NSTAGE * (128 + 256) * ROWB;   // 92160
    const int SM_256_128 = NSTAGE * (256 + 128) * ROWB;   // 92160
    const int SM_128_192 = NSTAGE * (128 + 192) * ROWB;   // 76800 (>= 64*194*4 = 49664 spline half-tile)

    cudaFuncSetAttribute(gemm_bf1<0,false,0,128,128>, cudaFuncAttributeMaxDynamicSharedMemorySize, SM_128_128);
    cudaFuncSetAttribute(gemm_bf1<2,false,0,128,256>, cudaFuncAttributeMaxDynamicSharedMemorySize, SM_128_256);
    cudaFuncSetAttribute(gemm_bf1<1,false,1,256,128>, cudaFuncAttributeMaxDynamicSharedMemorySize, SM_256_128);
    cudaFuncSetAttribute(gemm_bf1<3,true ,1,256,128>, cudaFuncAttributeMaxDynamicSharedMemorySize, SM_256_128);
    cudaFuncSetAttribute(gemm_bf1<3,false,1,256,128>, cudaFuncAttributeMaxDynamicSharedMemorySize, SM_256_128);
    cudaFuncSetAttribute(gemm_bf1<5,false,2,128,192>, cudaFuncAttributeMaxDynamicSharedMemorySize, SM_128_192);

    __nv_bfloat16 *A, *X, *Y, *Wc, *Wh, *Wb, *Wo;
    float *t, *sg, *cdfb, *pb;
    cudaGetSymbolAddress((void**)&A, g_A);
    cudaGetSymbolAddress((void**)&X, g_X);
    cudaGetSymbolAddress((void**)&Y, g_Y);
    cudaGetSymbolAddress((void**)&Wc, g_Wcat);
    cudaGetSymbolAddress((void**)&Wh, g_Whh);
    cudaGetSymbolAddress((void**)&Wb, g_Wcb);
    cudaGetSymbolAddress((void**)&Wo, g_Wout);
    cudaGetSymbolAddress((void**)&t, g_t);
    cudaGetSymbolAddress((void**)&sg, g_sg);
    cudaGetSymbolAddress((void**)&cdfb, g_CDF);
    cudaGetSymbolAddress((void**)&pb, g_pb);

    // 1) preps
    prepA   <<<(B_*KIN + 255) / 256, 256>>>(pred, ctx);
    prepWcat<<<(H_*KIN + 255) / 256, 256>>>(W_in, Wc_in);
    prepWhh <<<(2*NBLK*HH + 255) / 256, 256>>>(Wb1, Wb2);
    prepWcb <<<(NBLK*HH + 255) / 256, 256>>>(Wcb);
    prepWout<<<((int)(((size_t)NOUTP*H_ + 255) / 256)), 256>>>(W_out);
    permB   <<<(10*H_ + 255) / 256, 256>>>(b_in, bc_in, bb1, bb2, bcb);

    // 2) t = [pred|ctx] @ Wcat + biases ; X = bf16(relu(t)); tbuf = t
    {
        dim3 g(H_ / 128, B_ / 128);   // (4, 128)
        gemm_bf1<0,false,0,128,128><<<g, 256, SM_128_128>>>(A, KIN, Wc, KIN,
            pb, 0, t, nullptr, nullptr, nullptr, X);
    }

    // 2b) all 3 gates at once: sg[:, i*512+j] = sigmoid(ctx @ Wcb_i + bcb_i)
    {
        dim3 g(NBLK*H_ / 256, B_ / 128);  // (6, 128)
        gemm_bf1<2,false,0,128,256><<<g, 256, SM_128_256>>>(A + F_, KIN,
            Wb, C_, pb + 7*H_, NBLK*H_, nullptr, sg, nullptr, nullptr, nullptr);
    }

    // 3) residual blocks (BM=256/BN=128: 64x64 warp tiles + fine K-limits)
    dim3 gHH(H_ / 128, B_ / 256);     // (4, 64)
    for (int i = 0; i < NBLK; i++) {
        gemm_bf1<1,false,1,256,128><<<gHH, 256, SM_256_128>>>(X, H_,
            Wh + (size_t)i*HH, H_,
            pb + (1+i)*H_, 0, nullptr, nullptr, nullptr, nullptr, Y);
        if (i < NBLK - 1)
            gemm_bf1<3,true,1,256,128><<<gHH, 256, SM_256_128>>>(Y, H_,
                Wh + (size_t)(NBLK + i)*HH, H_,
                pb + (4+i)*H_, NBLK*H_, t, sg + i*H_, nullptr, nullptr, X);
        else
            gemm_bf1<3,false,1,256,128><<<gHH, 256, SM_256_128>>>(Y, H_,
                Wh + (size_t)(NBLK + i)*HH, H_,
                pb + (4+i)*H_, NBLK*H_, t, sg + i*H_, nullptr, nullptr, X);
    }

    // 4) out GEMM + fused spline: cdf[b,f] directly (no P materialization)
    {
        dim3 g(NOUTP / 192, B_ / 128);   // (32, 128)
        gemm_bf1<5,false,2,128,192><<<g, 256, SM_128_192>>>(X, H_, Wo, H_,
            b_out, 0, nullptr, nullptr, pred, cdfb, nullptr);
    }

    // 5) product over features
    prod_kernel<<<B_ / 4, 256>>>(cdfb, out);
}

// round 16
// speedup vs baseline: 1.5312x; 1.5312x over previous
#include <cuda_runtime.h>
#include <cuda_bf16.h>
#include <math.h>
#include <stdint.h>

#define B_    16384
#define F_    64
#define H_    512
#define C_    512
#define NBINS 30
#define MULT_ 91
#define MP_   96
#define NOUTP (F_*MP_)     // 6144
#define KIN   (F_+C_)      // 576
#define NBLK  3
#define HH    (H_*H_)

// ---------------- device scratch ----------------
__device__ __nv_bfloat16 g_A[B_*KIN];
__device__ __nv_bfloat16 g_X[B_*H_];
__device__ __nv_bfloat16 g_Y[B_*H_];
__device__ float g_t [B_*H_];
__device__ float g_sg[(size_t)B_*NBLK*H_];          // all 3 gates, row stride 1536
__device__ float g_CDF[(size_t)B_*F_];              // per-(b,f) spline CDF
__device__ float g_pb[10*H_];                       // permuted biases
__device__ __nv_bfloat16 g_Wcat[H_*KIN];
__device__ __nv_bfloat16 g_Whh[2*NBLK*HH];
__device__ __nv_bfloat16 g_Wcb[NBLK*HH];
__device__ __nv_bfloat16 g_Wout[(size_t)NOUTP*H_];

// ---------------- degree-sort permutation (MADE degrees d(j)=j%63+1) ----------------
__host__ __device__ __forceinline__ int deg_s(int s)  { return (s < 72) ? s / 9 + 1 : s / 8; }
__host__ __device__ __forceinline__ int cum_d(int d)  { return 8 * d + (d < 8 ? d : 8); }
__host__ __device__ __forceinline__ int perm_s(int s) {
    int d = deg_s(s);
    int r = (s < 72) ? s % 9 : (s & 7);
    return (d - 1) + 63 * r;
}

// ---------------- helpers ----------------
__device__ __forceinline__ uint32_t smem_u32(const void* p) {
    uint32_t a;
    asm("{ .reg .u64 t; cvta.to.shared.u64 t, %1; cvt.u32.u64 %0, t; }" : "=r"(a) : "l"(p));
    return a;
}
__device__ __forceinline__ void cp16(uint32_t dst, const void* src) {
    asm volatile("cp.async.cg.shared.global [%0], [%1], 16;" :: "r"(dst), "l"(src));
}
#define CP_COMMIT() asm volatile("cp.async.commit_group;" ::: "memory")
#define CP_WAIT(n)  asm volatile("cp.async.wait_group %0;" :: "n"(n) : "memory")

__device__ __forceinline__ void ldsm4(uint32_t& r0, uint32_t& r1, uint32_t& r2, uint32_t& r3,
                                      uint32_t addr) {
    asm volatile("ldmatrix.sync.aligned.m8n8.x4.shared.b16 {%0,%1,%2,%3}, [%4];"
                 : "=r"(r0), "=r"(r1), "=r"(r2), "=r"(r3) : "r"(addr));
}
__device__ __forceinline__ void mma16816(float* c, const uint32_t* a, const uint32_t* b) {
    asm volatile(
        "mma.sync.aligned.m16n8k16.row.col.f32.bf16.bf16.f32 "
        "{%0,%1,%2,%3}, {%4,%5,%6,%7}, {%8,%9}, {%0,%1,%2,%3};"
        : "+f"(c[0]), "+f"(c[1]), "+f"(c[2]), "+f"(c[3])
        : "r"(a[0]), "r"(a[1]), "r"(a[2]), "r"(a[3]), "r"(b[0]), "r"(b[1]));
}
__device__ __forceinline__ float softplusf(float x) {
    return fmaxf(x, 0.f) + log1pf(expf(-fabsf(x)));
}

// RQ spline for one (row, feature): pp = raw GEMM outputs, bo = b_out slice
__device__ __forceinline__ float spline_eval(const float* __restrict__ pp,
                                             const float* __restrict__ bo, float x) {
    if (x == 1.0f) return 1.0f;
    const float scale = 0.04419417382415922f;  // 1/sqrt(512)
    float ew[NBINS], mx = -1e30f;
    #pragma unroll
    for (int k = 0; k < NBINS; k++) { ew[k] = (pp[k] + bo[k]) * scale; mx = fmaxf(mx, ew[k]); }
    float s = 0.f;
    #pragma unroll
    for (int k = 0; k < NBINS; k++) { ew[k] = expf(ew[k] - mx); s += ew[k]; }
    float inv = (1.f - 1e-3f * NBINS) / s;
    float cw[NBINS + 1];
    cw[0] = 0.f;
    float run = 0.f;
    #pragma unroll
    for (int k = 0; k < NBINS; k++) { run += 1e-3f + ew[k] * inv; cw[k + 1] = run; }
    cw[NBINS] = 1.f;

    float eh[NBINS];
    mx = -1e30f;
    #pragma unroll
    for (int k = 0; k < NBINS; k++) { eh[k] = (pp[NBINS + k] + bo[NBINS + k]) * scale; mx = fmaxf(mx, eh[k]); }
    s = 0.f;
    #pragma unroll
    for (int k = 0; k < NBINS; k++) { eh[k] = expf(eh[k] - mx); s += eh[k]; }
    inv = (1.f - 1e-3f * NBINS) / s;
    float ch[NBINS + 1];
    ch[0] = 0.f;
    run = 0.f;
    #pragma unroll
    for (int k = 0; k < NBINS; k++) { run += 1e-3f + eh[k] * inv; ch[k + 1] = run; }
    ch[NBINS] = 1.f;

    int cnt = 0;
    #pragma unroll
    for (int k = 0; k <= NBINS; k++) {
        float loc = (k == NBINS) ? (1.f + 1e-6f) : cw[k];
        cnt += (x >= loc) ? 1 : 0;
    }
    int idx = min(max(cnt - 1, 0), NBINS - 1);

    float in_cw = cw[idx], in_w = cw[idx + 1] - cw[idx];
    float in_ch = ch[idx], in_h = ch[idx + 1] - ch[idx];
    float d0 = 1e-3f + softplusf(pp[2 * NBINS + idx]     + bo[2 * NBINS + idx]);
    float d1 = 1e-3f + softplusf(pp[2 * NBINS + idx + 1] + bo[2 * NBINS + idx + 1]);

    float delta = in_h / in_w;
    float theta = (x - in_cw) / in_w;
    float tt = theta * (1.f - theta);
    float num = in_h * (delta * theta * theta + d0 * tt);
    float den = delta + (d0 + d1 - 2.f * delta) * tt;
    return in_ch + num / den;
}

// ---------------- prep kernels (mask + permute + transpose; all bf16) ----------------
__global__ void prepA(const float* __restrict__ pred, const float* __restrict__ ctx) {
    int i = blockIdx.x * blockDim.x + threadIdx.x;
    if (i >= B_*KIN) return;
    int r = i / KIN, c = i % KIN;
    float v = (c < F_) ? pred[r*F_ + c] : ctx[r*C_ + (c - F_)];
    g_A[i] = __float2bfloat16(v);
}
__global__ void prepWcat(const float* __restrict__ W_in, const float* __restrict__ Wc_in) {
    int i = blockIdx.x * blockDim.x + threadIdx.x;
    if (i >= H_*KIN) return;
    int n = i / KIN, k = i % KIN;
    int no = perm_s(n), dn = deg_s(n);
    float v;
    if (k < F_) { v = (dn >= k + 1) ? W_in[k*H_ + no] : 0.f; }
    else        { v = Wc_in[(k - F_)*H_ + no]; }
    g_Wcat[i] = __float2bfloat16(v);
}
__global__ void prepWhh(const float* __restrict__ Wb1, const float* __restrict__ Wb2) {
    int i = blockIdx.x * blockDim.x + threadIdx.x;
    if (i >= 2*NBLK*HH) return;
    int mat = i / HH, rem = i % HH;
    int n = rem / H_, k = rem % H_;
    const float* W = (mat < NBLK) ? (Wb1 + (size_t)mat*HH) : (Wb2 + (size_t)(mat - NBLK)*HH);
    float v = (deg_s(k) <= deg_s(n)) ? W[perm_s(k)*H_ + perm_s(n)] : 0.f;
    g_Whh[i] = __float2bfloat16(v);
}
__global__ void prepWcb(const float* __restrict__ Wcb) {
    int i = blockIdx.x * blockDim.x + threadIdx.x;
    if (i >= NBLK*HH) return;
    int mat = i / HH, rem = i % HH;
    int n = rem / H_, k = rem % H_;
    g_Wcb[i] = __float2bfloat16(Wcb[(size_t)mat*HH + k*H_ + perm_s(n)]);
}
__global__ void prepWout(const float* __restrict__ W_out) {
    size_t i = (size_t)blockIdx.x * blockDim.x + threadIdx.x;
    if (i >= (size_t)NOUTP*H_) return;
    int n = (int)(i / H_), k = (int)(i % H_);
    int f = n / MP_, j = n % MP_;
    float v = 0.f;
    if (j < MULT_ && f >= deg_s(k)) v = W_out[(size_t)perm_s(k)*(F_*MULT_) + f*MULT_ + j];
    g_Wout[i] = __float2bfloat16(v);
}
__global__ void permB(const float* __restrict__ b_in, const float* __restrict__ bc_in,
                      const float* __restrict__ bb1, const float* __restrict__ bb2,
                      const float* __restrict__ bcb) {
    int i = blockIdx.x * blockDim.x + threadIdx.x;
    if (i >= 10*H_) return;
    int v = i / H_, s = i % H_, j = perm_s(s);
    float x;
    if      (v == 0) x = b_in[j] + bc_in[j];
    else if (v <= 3) x = bb1[(v-1)*H_ + j];
    else if (v <= 6) x = bb2[(v-4)*H_ + j];
    else             x = bcb[(v-7)*H_ + j];
    g_pb[i] = x;
}

// ---------------- pure-bf16 mma.sync GEMM, 64x32 warp tiles, fused epilogues ----------------
// All tiles BM=128. Warps: 2 rows x 4 cols; warp tile 64 x (BN/4).
// BN=128 variants: NT=4, acc=64 regs -> 2 CTAs/SM without spills.
// Spline variant BN=192: NT=6, acc=96 regs -> 1 CTA/SM (proven round-14 shape).
// EPI: 0=t-init  1=relu  2=sigmoid  3=GLU residual  5=spline
// KMODE: 0=full K  1=HH (N=sorted hidden)  2=out (N=2 features/tile, BN=192)
#define BK 32
#define NSTAGE 3
#define ROWB 80

template<int BNv>
__device__ __forceinline__ void issue_stage_t(
    uint32_t sb, const __nv_bfloat16* A, int lda,
    const __nv_bfloat16* Bh, int K,
    int m0, int n0, int k0, int tid)
{
    constexpr int A_B = 128 * ROWB;
    constexpr int NCP = (128 + BNv) * 4;
    #pragma unroll
    for (int it = 0; it < NCP/256; it++) {
        int i = tid + it * 256;
        if (i < 128*4) {
            int r = i >> 2, c = i & 3;
            cp16(sb + r*ROWB + c*16, A + (size_t)(m0 + r) * lda + k0 + c*8);
        } else {
            int j = i - 128*4;
            int r = j >> 2, c = j & 3;
            cp16(sb + A_B + r*ROWB + c*16, Bh + (size_t)(n0 + r) * K + k0 + c*8);
        }
    }
}

template<int EPI, bool RELUF, int KMODE, int BNv, int OCC>
__global__ void __launch_bounds__(256, OCC) gemm_bf1(
    const __nv_bfloat16* __restrict__ A, int lda,
    const __nv_bfloat16* __restrict__ Bh, int K,
    const float* __restrict__ bias1, int sg_ld,
    float* __restrict__ tbuf, float* __restrict__ sgbuf,
    const float* __restrict__ pred, float* __restrict__ cdf,
    __nv_bfloat16* __restrict__ outX)
{
    constexpr int WNW = BNv / 4;         // warp n-width
    constexpr int NT  = WNW / 8;
    constexpr int A_B = 128 * ROWB;
    constexpr int B_B = BNv * ROWB;
    constexpr int STG = A_B + B_B;

    extern __shared__ char smem[];
    uint32_t sbase = smem_u32(smem);
    int tid = threadIdx.x;
    int lane = tid & 31, wid = tid >> 5;
    int wm = (wid >> 2) * 64;            // 2 warp rows
    int wn = (wid & 3) * WNW;            // 4 warp cols
    int m0 = blockIdx.y * 128, n0 = blockIdx.x * BNv;

    // degree-limited K (skipped rows are exact zeros in sorted weights)
    int klim = K;
    if (KMODE == 1) {
        int dmax = deg_s(n0 + BNv - 1);
        klim = min(K, (cum_d(dmax) + BK - 1) & ~(BK - 1));
    } else if (KMODE == 2) {
        int T = 2 * blockIdx.x + 1;
        if (T > 63) T = 63;
        klim = min(K, (cum_d(T) + BK - 1) & ~(BK - 1));
    }
    const int kiters = klim / BK;

    float acc[4][NT][4];
    #pragma unroll
    for (int mt = 0; mt < 4; mt++)
        #pragma unroll
        for (int nt = 0; nt < NT; nt++)
            #pragma unroll
            for (int q = 0; q < 4; q++) acc[mt][nt][q] = 0.f;

    #pragma unroll
    for (int s = 0; s < NSTAGE - 1; s++) {
        if (s < kiters)
            issue_stage_t<BNv>(sbase + s*STG, A, lda, Bh, K, m0, n0, s*BK, tid);
        CP_COMMIT();
    }

    int a_row = (lane & 15);
    uint32_t a_colb = (lane >> 4) * 16;
    int b_row = ((lane >> 4) << 3) + (lane & 7);
    uint32_t b_colb = ((lane >> 3) & 1) * 16;

    for (int ki = 0; ki < kiters; ki++) {
        CP_WAIT(NSTAGE - 2);
        __syncthreads();

        int kn = ki + NSTAGE - 1;
        if (kn < kiters)
            issue_stage_t<BNv>(sbase + (kn % NSTAGE)*STG, A, lda, Bh, K,
                               m0, n0, kn*BK, tid);
        CP_COMMIT();

        uint32_t sb = sbase + (ki % NSTAGE) * STG;
        #pragma unroll
        for (int ks = 0; ks < 2; ks++) {
            uint32_t kb = ks * 32;
            uint32_t ah[4][4];
            #pragma unroll
            for (int mt = 0; mt < 4; mt++) {
                uint32_t ar = (uint32_t)(wm + mt*16 + a_row) * ROWB + kb + a_colb;
                ldsm4(ah[mt][0], ah[mt][1], ah[mt][2], ah[mt][3], sb + ar);
            }
            uint32_t bh[NT][2];
            #pragma unroll
            for (int bt = 0; bt < NT/2; bt++) {
                uint32_t br = (uint32_t)(wn + bt*16 + b_row) * ROWB + kb + b_colb;
                ldsm4(bh[2*bt][0], bh[2*bt][1], bh[2*bt+1][0], bh[2*bt+1][1], sb + A_B + br);
            }
            #pragma unroll
            for (int mt = 0; mt < 4; mt++)
                #pragma unroll
                for (int nt = 0; nt < NT; nt++)
                    mma16816(acc[mt][nt], ah[mt], bh[nt]);
        }
        __syncthreads();
    }

    if (EPI == 5) {
        // ---- fused spline epilogue (BNv=192 = 2 features) ----
        constexpr int LDD = 194;
        float* Dsm = reinterpret_cast<float*>(smem);
        #pragma unroll
        for (int mt = 0; mt < 4; mt++)
            #pragma unroll
            for (int nt = 0; nt < NT; nt++) {
                int rl = wm + mt*16 + (lane >> 2);
                int cl = wn + nt*8 + (lane & 3) * 2;
                *reinterpret_cast<float2*>(&Dsm[rl*LDD + cl])     = make_float2(acc[mt][nt][0], acc[mt][nt][1]);
                *reinterpret_cast<float2*>(&Dsm[(rl+8)*LDD + cl]) = make_float2(acc[mt][nt][2], acc[mt][nt][3]);
            }
        __syncthreads();

        int row = tid >> 1, feat = tid & 1;
        int gf = 2 * blockIdx.x + feat;
        int gr = m0 + row;
        float x = pred[gr * F_ + gf];
        float cdfv = spline_eval(Dsm + row * LDD + feat * MP_, bias1 + gf * MULT_, x);
        cdf[gr * F_ + gf] = cdfv;
        return;
    }

    // ---- standard epilogues ----
    #pragma unroll
    for (int mt = 0; mt < 4; mt++)
        #pragma unroll
        for (int nt = 0; nt < NT; nt++) {
            #pragma unroll
            for (int half = 0; half < 2; half++) {
                float v0 = acc[mt][nt][half*2], v1 = acc[mt][nt][half*2+1];
                int gr = m0 + wm + mt*16 + (lane >> 2) + half*8;
                int gc = n0 + wn + nt*8 + (lane & 3) * 2;
                if (EPI == 0) {
                    v0 += bias1[gc]; v1 += bias1[gc+1];
                    int g = gr * H_ + gc;
                    *reinterpret_cast<float2*>(&tbuf[g]) = make_float2(v0, v1);
                    __nv_bfloat162 hv;
                    hv.x = __float2bfloat16(fmaxf(v0, 0.f));
                    hv.y = __float2bfloat16(fmaxf(v1, 0.f));
                    *reinterpret_cast<__nv_bfloat162*>(&outX[g]) = hv;
                } else if (EPI == 1) {
                    v0 += bias1[gc]; v1 += bias1[gc+1];
                    int g = gr * H_ + gc;
                    __nv_bfloat162 hv;
                    hv.x = __float2bfloat16(fmaxf(v0, 0.f));
                    hv.y = __float2bfloat16(fmaxf(v1, 0.f));
                    *reinterpret_cast<__nv_bfloat162*>(&outX[g]) = hv;
                } else if (EPI == 2) {
                    v0 += bias1[gc]; v1 += bias1[gc+1];
                    float s0 = 1.f / (1.f + expf(-v0)), s1 = 1.f / (1.f + expf(-v1));
                    *reinterpret_cast<float2*>(&sgbuf[(size_t)gr * sg_ld + gc]) = make_float2(s0, s1);
                } else if (EPI == 3) {
                    v0 += bias1[gc]; v1 += bias1[gc+1];
                    int g = gr * H_ + gc;
                    float2 tv = *reinterpret_cast<const float2*>(&tbuf[g]);
                    float2 sv = *reinterpret_cast<const float2*>(&sgbuf[(size_t)gr * sg_ld + gc]);
                    float t0 = tv.x + v0 * sv.x, t1 = tv.y + v1 * sv.y;
                    *reinterpret_cast<float2*>(&tbuf[g]) = make_float2(t0, t1);
                    float z0 = RELUF ? fmaxf(t0, 0.f) : t0;
                    float z1 = RELUF ? fmaxf(t1, 0.f) : t1;
                    __nv_bfloat162 hv;
                    hv.x = __float2bfloat16(z0);
                    hv.y = __float2bfloat16(z1);
                    *reinterpret_cast<__nv_bfloat162*>(&outX[g]) = hv;
                }
            }
        }
}

// ---------------- product over features (same double shfl-tree order) ----------------
__global__ void prod_kernel(const float* __restrict__ cdf, float* __restrict__ out) {
    int tid = threadIdx.x;
    int r = tid >> 6, f = tid & 63;
    int b = blockIdx.x * 4 + r;
    double vv = (double)cdf[(size_t)b * F_ + f];
    #pragma unroll
    for (int o = 16; o > 0; o >>= 1)
        vv *= __shfl_xor_sync(0xffffffffu, vv, o);
    __shared__ double sred[8];
    int w = tid >> 5;
    if ((tid & 31) == 0) sred[w] = vv;
    __syncthreads();
    if (f == 0) out[b] = (float)(sred[2*r] * sred[2*r + 1]);
}

// ---------------- launch ----------------
extern "C" void kernel_launch(void* const* d_in, const int* in_sizes, int n_in,
                              void* d_out, int out_size) {
    const float* pred  = (const float*)d_in[0];
    const float* ctx   = (const float*)d_in[1];
    const float* W_in  = (const float*)d_in[2];
    const float* b_in  = (const float*)d_in[3];
    const float* Wc_in = (const float*)d_in[4];
    const float* bc_in = (const float*)d_in[5];
    const float* Wb1   = (const float*)d_in[6];
    const float* bb1   = (const float*)d_in[7];
    const float* Wb2   = (const float*)d_in[8];
    const float* bb2   = (const float*)d_in[9];
    const float* Wcb   = (const float*)d_in[10];
    const float* bcb   = (const float*)d_in[11];
    const float* W_out = (const float*)d_in[12];
    const float* b_out = (const float*)d_in[13];
    float* out = (float*)d_out;

    const int SM_BN128 = NSTAGE * (128 + 128) * ROWB;   // 61440; x2 CTAs = 122880 <= 227K
    const int SM_BN192 = NSTAGE * (128 + 192) * ROWB;   // 76800 (>= 128*194*4? no: spline tile 99328)
    const int SM_SPL   = 128 * 194 * 4;                 // 99328
    const int SM_OUT   = (SM_BN192 > SM_SPL) ? SM_BN192 : SM_SPL;  // 99328

    cudaFuncSetAttribute(gemm_bf1<0,false,0,128,2>, cudaFuncAttributeMaxDynamicSharedMemorySize, SM_BN128);
    cudaFuncSetAttribute(gemm_bf1<2,false,0,128,2>, cudaFuncAttributeMaxDynamicSharedMemorySize, SM_BN128);
    cudaFuncSetAttribute(gemm_bf1<1,false,1,128,2>, cudaFuncAttributeMaxDynamicSharedMemorySize, SM_BN128);
    cudaFuncSetAttribute(gemm_bf1<3,true ,1,128,2>, cudaFuncAttributeMaxDynamicSharedMemorySize, SM_BN128);
    cudaFuncSetAttribute(gemm_bf1<3,false,1,128,2>, cudaFuncAttributeMaxDynamicSharedMemorySize, SM_BN128);
    cudaFuncSetAttribute(gemm_bf1<5,false,2,192,1>, cudaFuncAttributeMaxDynamicSharedMemorySize, SM_OUT);

    __nv_bfloat16 *A, *X, *Y, *Wc, *Wh, *Wb, *Wo;
    float *t, *sg, *cdfb, *pb;
    cudaGetSymbolAddress((void**)&A, g_A);
    cudaGetSymbolAddress((void**)&X, g_X);
    cudaGetSymbolAddress((void**)&Y, g_Y);
    cudaGetSymbolAddress((void**)&Wc, g_Wcat);
    cudaGetSymbolAddress((void**)&Wh, g_Whh);
    cudaGetSymbolAddress((void**)&Wb, g_Wcb);
    cudaGetSymbolAddress((void**)&Wo, g_Wout);
    cudaGetSymbolAddress((void**)&t, g_t);
    cudaGetSymbolAddress((void**)&sg, g_sg);
    cudaGetSymbolAddress((void**)&cdfb, g_CDF);
    cudaGetSymbolAddress((void**)&pb, g_pb);

    // 1) preps
    prepA   <<<(B_*KIN + 255) / 256, 256>>>(pred, ctx);
    prepWcat<<<(H_*KIN + 255) / 256, 256>>>(W_in, Wc_in);
    prepWhh <<<(2*NBLK*HH + 255) / 256, 256>>>(Wb1, Wb2);
    prepWcb <<<(NBLK*HH + 255) / 256, 256>>>(Wcb);
    prepWout<<<((int)(((size_t)NOUTP*H_ + 255) / 256)), 256>>>(W_out);
    permB   <<<(10*H_ + 255) / 256, 256>>>(b_in, bc_in, bb1, bb2, bcb);

    // 2) t = [pred|ctx] @ Wcat + biases ; X = bf16(relu(t)); tbuf = t
    {
        dim3 g(H_ / 128, B_ / 128);   // (4, 128)
        gemm_bf1<0,false,0,128,2><<<g, 256, SM_BN128>>>(A, KIN, Wc, KIN,
            pb, 0, t, nullptr, nullptr, nullptr, X);
    }

    // 2b) all 3 gates at once: sg[:, i*512+j] = sigmoid(ctx @ Wcb_i + bcb_i)
    {
        dim3 g(NBLK*H_ / 128, B_ / 128);  // (12, 128)
        gemm_bf1<2,false,0,128,2><<<g, 256, SM_BN128>>>(A + F_, KIN,
            Wb, C_, pb + 7*H_, NBLK*H_, nullptr, sg, nullptr, nullptr, nullptr);
    }

    // 3) residual blocks (BM=128/BN=128: fine K-limits + 2 CTAs/SM)
    dim3 gHH(H_ / 128, B_ / 128);     // (4, 128)
    for (int i = 0; i < NBLK; i++) {
        gemm_bf1<1,false,1,128,2><<<gHH, 256, SM_BN128>>>(X, H_,
            Wh + (size_t)i*HH, H_,
            pb + (1+i)*H_, 0, nullptr, nullptr, nullptr, nullptr, Y);
        if (i < NBLK - 1)
            gemm_bf1<3,true,1,128,2><<<gHH, 256, SM_BN128>>>(Y, H_,
                Wh + (size_t)(NBLK + i)*HH, H_,
                pb + (4+i)*H_, NBLK*H_, t, sg + i*H_, nullptr, nullptr, X);
        else
            gemm_bf1<3,false,1,128,2><<<gHH, 256, SM_BN128>>>(Y, H_,
                Wh + (size_t)(NBLK + i)*HH, H_,
                pb + (4+i)*H_, NBLK*H_, t, sg + i*H_, nullptr, nullptr, X);
    }

    // 4) out GEMM + fused spline (proven round-14 shape, occ=1)
    {
        dim3 g(NOUTP / 192, B_ / 128);   // (32, 128)
        gemm_bf1<5,false,2,192,1><<<g, 256, SM_OUT>>>(X, H_, Wo, H_,
            b_out, 0, nullptr, nullptr, pred, cdfb, nullptr);
    }

    // 5) product over features
    prod_kernel<<<B_ / 4, 256>>>(cdfb, out);
}

// round 17
// speedup vs baseline: 1.5773x; 1.0301x over previous
#include <cuda_runtime.h>
#include <cuda_bf16.h>
#include <math.h>
#include <stdint.h>

#define B_    16384
#define F_    64
#define H_    512
#define C_    512
#define NBINS 30
#define MULT_ 91
#define MP_   96
#define NOUTP (F_*MP_)     // 6144
#define KIN   (F_+C_)      // 576
#define NBLK  3
#define HH    (H_*H_)

// ---------------- device scratch ----------------
__device__ __nv_bfloat16 g_A[B_*KIN];
__device__ __nv_bfloat16 g_X[B_*H_];
__device__ __nv_bfloat16 g_Y[B_*H_];
__device__ float g_t [B_*H_];
__device__ float g_sg[(size_t)B_*NBLK*H_];          // all 3 gates, row stride 1536
__device__ float g_CDF[(size_t)B_*F_];              // per-(b,f) spline CDF
__device__ float g_pb[10*H_];                       // permuted biases
__device__ __nv_bfloat16 g_Wcat[H_*KIN];
__device__ __nv_bfloat16 g_Whh[2*NBLK*HH];
__device__ __nv_bfloat16 g_Wcb[NBLK*HH];
__device__ __nv_bfloat16 g_Wout[(size_t)NOUTP*H_];

// ---------------- degree-sort permutation (MADE degrees d(j)=j%63+1) ----------------
__host__ __device__ __forceinline__ int deg_s(int s)  { return (s < 72) ? s / 9 + 1 : s / 8; }
__host__ __device__ __forceinline__ int cum_d(int d)  { return 8 * d + (d < 8 ? d : 8); }
__host__ __device__ __forceinline__ int perm_s(int s) {
    int d = deg_s(s);
    int r = (s < 72) ? s % 9 : (s & 7);
    return (d - 1) + 63 * r;
}

// ---------------- helpers ----------------
__device__ __forceinline__ uint32_t smem_u32(const void* p) {
    uint32_t a;
    asm("{ .reg .u64 t; cvta.to.shared.u64 t, %1; cvt.u32.u64 %0, t; }" : "=r"(a) : "l"(p));
    return a;
}
__device__ __forceinline__ void cp16(uint32_t dst, const void* src) {
    asm volatile("cp.async.cg.shared.global [%0], [%1], 16;" :: "r"(dst), "l"(src));
}
#define CP_COMMIT() asm volatile("cp.async.commit_group;" ::: "memory")
#define CP_WAIT(n)  asm volatile("cp.async.wait_group %0;" :: "n"(n) : "memory")

__device__ __forceinline__ void ldsm4(uint32_t& r0, uint32_t& r1, uint32_t& r2, uint32_t& r3,
                                      uint32_t addr) {
    asm volatile("ldmatrix.sync.aligned.m8n8.x4.shared.b16 {%0,%1,%2,%3}, [%4];"
                 : "=r"(r0), "=r"(r1), "=r"(r2), "=r"(r3) : "r"(addr));
}
__device__ __forceinline__ void ldsm2(uint32_t& r0, uint32_t& r1, uint32_t addr) {
    asm volatile("ldmatrix.sync.aligned.m8n8.x2.shared.b16 {%0,%1}, [%2];"
                 : "=r"(r0), "=r"(r1) : "r"(addr));
}
__device__ __forceinline__ void mma16816(float* c, const uint32_t* a, const uint32_t* b) {
    asm volatile(
        "mma.sync.aligned.m16n8k16.row.col.f32.bf16.bf16.f32 "
        "{%0,%1,%2,%3}, {%4,%5,%6,%7}, {%8,%9}, {%0,%1,%2,%3};"
        : "+f"(c[0]), "+f"(c[1]), "+f"(c[2]), "+f"(c[3])
        : "r"(a[0]), "r"(a[1]), "r"(a[2]), "r"(a[3]), "r"(b[0]), "r"(b[1]));
}
__device__ __forceinline__ float softplusf(float x) {
    return fmaxf(x, 0.f) + log1pf(expf(-fabsf(x)));
}

// RQ spline for one (row, feature): pp = raw GEMM outputs, bo = b_out slice
__device__ __forceinline__ float spline_eval(const float* __restrict__ pp,
                                             const float* __restrict__ bo, float x) {
    if (x == 1.0f) return 1.0f;
    const float scale = 0.04419417382415922f;  // 1/sqrt(512)
    float ew[NBINS], mx = -1e30f;
    #pragma unroll
    for (int k = 0; k < NBINS; k++) { ew[k] = (pp[k] + bo[k]) * scale; mx = fmaxf(mx, ew[k]); }
    float s = 0.f;
    #pragma unroll
    for (int k = 0; k < NBINS; k++) { ew[k] = expf(ew[k] - mx); s += ew[k]; }
    float inv = (1.f - 1e-3f * NBINS) / s;
    float cw[NBINS + 1];
    cw[0] = 0.f;
    float run = 0.f;
    #pragma unroll
    for (int k = 0; k < NBINS; k++) { run += 1e-3f + ew[k] * inv; cw[k + 1] = run; }
    cw[NBINS] = 1.f;

    float eh[NBINS];
    mx = -1e30f;
    #pragma unroll
    for (int k = 0; k < NBINS; k++) { eh[k] = (pp[NBINS + k] + bo[NBINS + k]) * scale; mx = fmaxf(mx, eh[k]); }
    s = 0.f;
    #pragma unroll
    for (int k = 0; k < NBINS; k++) { eh[k] = expf(eh[k] - mx); s += eh[k]; }
    inv = (1.f - 1e-3f * NBINS) / s;
    float ch[NBINS + 1];
    ch[0] = 0.f;
    run = 0.f;
    #pragma unroll
    for (int k = 0; k < NBINS; k++) { run += 1e-3f + eh[k] * inv; ch[k + 1] = run; }
    ch[NBINS] = 1.f;

    int cnt = 0;
    #pragma unroll
    for (int k = 0; k <= NBINS; k++) {
        float loc = (k == NBINS) ? (1.f + 1e-6f) : cw[k];
        cnt += (x >= loc) ? 1 : 0;
    }
    int idx = min(max(cnt - 1, 0), NBINS - 1);

    float in_cw = cw[idx], in_w = cw[idx + 1] - cw[idx];
    float in_ch = ch[idx], in_h = ch[idx + 1] - ch[idx];
    float d0 = 1e-3f + softplusf(pp[2 * NBINS + idx]     + bo[2 * NBINS + idx]);
    float d1 = 1e-3f + softplusf(pp[2 * NBINS + idx + 1] + bo[2 * NBINS + idx + 1]);

    float delta = in_h / in_w;
    float theta = (x - in_cw) / in_w;
    float tt = theta * (1.f - theta);
    float num = in_h * (delta * theta * theta + d0 * tt);
    float den = delta + (d0 + d1 - 2.f * delta) * tt;
    return in_ch + num / den;
}

// ---------------- prep kernels (mask + permute + transpose; all bf16) ----------------
__global__ void prepA(const float* __restrict__ pred, const float* __restrict__ ctx) {
    int i = blockIdx.x * blockDim.x + threadIdx.x;
    if (i >= B_*KIN) return;
    int r = i / KIN, c = i % KIN;
    float v = (c < F_) ? pred[r*F_ + c] : ctx[r*C_ + (c - F_)];
    g_A[i] = __float2bfloat16(v);
}
__global__ void prepWcat(const float* __restrict__ W_in, const float* __restrict__ Wc_in) {
    int i = blockIdx.x * blockDim.x + threadIdx.x;
    if (i >= H_*KIN) return;
    int n = i / KIN, k = i % KIN;
    int no = perm_s(n), dn = deg_s(n);
    float v;
    if (k < F_) { v = (dn >= k + 1) ? W_in[k*H_ + no] : 0.f; }
    else        { v = Wc_in[(k - F_)*H_ + no]; }
    g_Wcat[i] = __float2bfloat16(v);
}
__global__ void prepWhh(const float* __restrict__ Wb1, const float* __restrict__ Wb2) {
    int i = blockIdx.x * blockDim.x + threadIdx.x;
    if (i >= 2*NBLK*HH) return;
    int mat = i / HH, rem = i % HH;
    int n = rem / H_, k = rem % H_;
    const float* W = (mat < NBLK) ? (Wb1 + (size_t)mat*HH) : (Wb2 + (size_t)(mat - NBLK)*HH);
    float v = (deg_s(k) <= deg_s(n)) ? W[perm_s(k)*H_ + perm_s(n)] : 0.f;
    g_Whh[i] = __float2bfloat16(v);
}
__global__ void prepWcb(const float* __restrict__ Wcb) {
    int i = blockIdx.x * blockDim.x + threadIdx.x;
    if (i >= NBLK*HH) return;
    int mat = i / HH, rem = i % HH;
    int n = rem / H_, k = rem % H_;
    g_Wcb[i] = __float2bfloat16(Wcb[(size_t)mat*HH + k*H_ + perm_s(n)]);
}
__global__ void prepWout(const float* __restrict__ W_out) {
    size_t i = (size_t)blockIdx.x * blockDim.x + threadIdx.x;
    if (i >= (size_t)NOUTP*H_) return;
    int n = (int)(i / H_), k = (int)(i % H_);
    int f = n / MP_, j = n % MP_;
    float v = 0.f;
    if (j < MULT_ && f >= deg_s(k)) v = W_out[(size_t)perm_s(k)*(F_*MULT_) + f*MULT_ + j];
    g_Wout[i] = __float2bfloat16(v);
}
__global__ void permB(const float* __restrict__ b_in, const float* __restrict__ bc_in,
                      const float* __restrict__ bb1, const float* __restrict__ bb2,
                      const float* __restrict__ bcb) {
    int i = blockIdx.x * blockDim.x + threadIdx.x;
    if (i >= 10*H_) return;
    int v = i / H_, s = i % H_, j = perm_s(s);
    float x;
    if      (v == 0) x = b_in[j] + bc_in[j];
    else if (v <= 3) x = bb1[(v-1)*H_ + j];
    else if (v <= 6) x = bb2[(v-4)*H_ + j];
    else             x = bcb[(v-7)*H_ + j];
    g_pb[i] = x;
}

// ---------------- pure-bf16 mma.sync GEMM, 2 CTAs/SM everywhere ----------------
// BM=128; warps 2 rows x 4 cols; warp tile 64 x (BN/4).
// BN=128: NT=4 (acc 64 regs). BN=96 (spline): NT=3 (acc 48 regs), ldsm2 tail.
// EPI: 0=t-init  1=relu  2=sigmoid  3=GLU residual  5=spline(1 feature/tile)
// KMODE: 0=full K  1=HH (N=sorted hidden)  2=out (feature = blockIdx.x)
#define BK 32
#define NSTAGE 3
#define ROWB 80

template<int BNv>
__device__ __forceinline__ void issue_stage_t(
    uint32_t sb, const __nv_bfloat16* A, int lda,
    const __nv_bfloat16* Bh, int K,
    int m0, int n0, int k0, int tid)
{
    constexpr int A_B = 128 * ROWB;
    constexpr int NCP = (128 + BNv) * 4;
    #pragma unroll
    for (int it = 0; it < (NCP + 255)/256; it++) {
        int i = tid + it * 256;
        if (i >= NCP) break;
        if (i < 128*4) {
            int r = i >> 2, c = i & 3;
            cp16(sb + r*ROWB + c*16, A + (size_t)(m0 + r) * lda + k0 + c*8);
        } else {
            int j = i - 128*4;
            int r = j >> 2, c = j & 3;
            cp16(sb + A_B + r*ROWB + c*16, Bh + (size_t)(n0 + r) * K + k0 + c*8);
        }
    }
}

template<int EPI, bool RELUF, int KMODE, int BNv, int OCC>
__global__ void __launch_bounds__(256, OCC) gemm_bf1(
    const __nv_bfloat16* __restrict__ A, int lda,
    const __nv_bfloat16* __restrict__ Bh, int K,
    const float* __restrict__ bias1, int sg_ld,
    float* __restrict__ tbuf, float* __restrict__ sgbuf,
    const float* __restrict__ pred, float* __restrict__ cdf,
    __nv_bfloat16* __restrict__ outX)
{
    constexpr int WNW = BNv / 4;         // warp n-width
    constexpr int NT  = WNW / 8;
    constexpr int A_B = 128 * ROWB;
    constexpr int STG = A_B + BNv * ROWB;

    extern __shared__ char smem[];
    uint32_t sbase = smem_u32(smem);
    int tid = threadIdx.x;
    int lane = tid & 31, wid = tid >> 5;
    int wm = (wid >> 2) * 64;
    int wn = (wid & 3) * WNW;
    int m0 = blockIdx.y * 128, n0 = blockIdx.x * BNv;

    // degree-limited K (skipped rows are exact zeros in sorted weights)
    int klim = K;
    if (KMODE == 1) {
        int dmax = deg_s(n0 + BNv - 1);
        klim = min(K, (cum_d(dmax) + BK - 1) & ~(BK - 1));
    } else if (KMODE == 2) {
        int T = blockIdx.x;                   // one feature per tile (BNv=96)
        if (T > 63) T = 63;
        klim = min(K, (cum_d(T) + BK - 1) & ~(BK - 1));
    }
    const int kiters = klim / BK;

    float acc[4][NT][4];
    #pragma unroll
    for (int mt = 0; mt < 4; mt++)
        #pragma unroll
        for (int nt = 0; nt < NT; nt++)
            #pragma unroll
            for (int q = 0; q < 4; q++) acc[mt][nt][q] = 0.f;

    #pragma unroll
    for (int s = 0; s < NSTAGE - 1; s++) {
        if (s < kiters)
            issue_stage_t<BNv>(sbase + s*STG, A, lda, Bh, K, m0, n0, s*BK, tid);
        CP_COMMIT();
    }

    int a_row = (lane & 15);
    uint32_t a_colb = (lane >> 4) * 16;
    int b_row = ((lane >> 4) << 3) + (lane & 7);
    uint32_t b_colb = ((lane >> 3) & 1) * 16;
    int l15 = lane & 15;                       // ldsm2 addressing (lanes 0-15 used)
    int b2_row = l15 & 7;
    uint32_t b2_colb = ((l15 >> 3) & 1) * 16;

    for (int ki = 0; ki < kiters; ki++) {
        CP_WAIT(NSTAGE - 2);
        __syncthreads();

        int kn = ki + NSTAGE - 1;
        if (kn < kiters)
            issue_stage_t<BNv>(sbase + (kn % NSTAGE)*STG, A, lda, Bh, K,
                               m0, n0, kn*BK, tid);
        CP_COMMIT();

        uint32_t sb = sbase + (ki % NSTAGE) * STG;
        #pragma unroll
        for (int ks = 0; ks < 2; ks++) {
            uint32_t kb = ks * 32;
            uint32_t ah[4][4];
            #pragma unroll
            for (int mt = 0; mt < 4; mt++) {
                uint32_t ar = (uint32_t)(wm + mt*16 + a_row) * ROWB + kb + a_colb;
                ldsm4(ah[mt][0], ah[mt][1], ah[mt][2], ah[mt][3], sb + ar);
            }
            uint32_t bh[NT][2];
            #pragma unroll
            for (int bt = 0; bt < NT/2; bt++) {
                uint32_t br = (uint32_t)(wn + bt*16 + b_row) * ROWB + kb + b_colb;
                ldsm4(bh[2*bt][0], bh[2*bt][1], bh[2*bt+1][0], bh[2*bt+1][1], sb + A_B + br);
            }
            if (NT & 1) {
                uint32_t br = (uint32_t)(wn + (NT-1)*8 + b2_row) * ROWB + kb + b2_colb;
                ldsm2(bh[NT-1][0], bh[NT-1][1], sb + A_B + br);
            }
            #pragma unroll
            for (int mt = 0; mt < 4; mt++)
                #pragma unroll
                for (int nt = 0; nt < NT; nt++)
                    mma16816(acc[mt][nt], ah[mt], bh[nt]);
        }
        __syncthreads();
    }

    if (EPI == 5) {
        // ---- fused spline epilogue: BNv=96 = ONE feature per tile ----
        constexpr int LDD = 98;
        float* Dsm = reinterpret_cast<float*>(smem);
        __syncthreads();   // mainloop smem reuse
        #pragma unroll
        for (int mt = 0; mt < 4; mt++)
            #pragma unroll
            for (int nt = 0; nt < NT; nt++) {
                int rl = wm + mt*16 + (lane >> 2);
                int cl = wn + nt*8 + (lane & 3) * 2;
                *reinterpret_cast<float2*>(&Dsm[rl*LDD + cl])     = make_float2(acc[mt][nt][0], acc[mt][nt][1]);
                *reinterpret_cast<float2*>(&Dsm[(rl+8)*LDD + cl]) = make_float2(acc[mt][nt][2], acc[mt][nt][3]);
            }
        __syncthreads();

        if (tid < 128) {
            int gf = blockIdx.x;
            int gr = m0 + tid;
            float x = pred[gr * F_ + gf];
            float cdfv = spline_eval(Dsm + tid * LDD, bias1 + gf * MULT_, x);
            cdf[gr * F_ + gf] = cdfv;
        }
        return;
    }

    // ---- standard epilogues ----
    #pragma unroll
    for (int mt = 0; mt < 4; mt++)
        #pragma unroll
        for (int nt = 0; nt < NT; nt++) {
            #pragma unroll
            for (int half = 0; half < 2; half++) {
                float v0 = acc[mt][nt][half*2], v1 = acc[mt][nt][half*2+1];
                int gr = m0 + wm + mt*16 + (lane >> 2) + half*8;
                int gc = n0 + wn + nt*8 + (lane & 3) * 2;
                if (EPI == 0) {
                    v0 += bias1[gc]; v1 += bias1[gc+1];
                    int g = gr * H_ + gc;
                    *reinterpret_cast<float2*>(&tbuf[g]) = make_float2(v0, v1);
                    __nv_bfloat162 hv;
                    hv.x = __float2bfloat16(fmaxf(v0, 0.f));
                    hv.y = __float2bfloat16(fmaxf(v1, 0.f));
                    *reinterpret_cast<__nv_bfloat162*>(&outX[g]) = hv;
                } else if (EPI == 1) {
                    v0 += bias1[gc]; v1 += bias1[gc+1];
                    int g = gr * H_ + gc;
                    __nv_bfloat162 hv;
                    hv.x = __float2bfloat16(fmaxf(v0, 0.f));
                    hv.y = __float2bfloat16(fmaxf(v1, 0.f));
                    *reinterpret_cast<__nv_bfloat162*>(&outX[g]) = hv;
                } else if (EPI == 2) {
                    v0 += bias1[gc]; v1 += bias1[gc+1];
                    float s0 = 1.f / (1.f + expf(-v0)), s1 = 1.f / (1.f + expf(-v1));
                    *reinterpret_cast<float2*>(&sgbuf[(size_t)gr * sg_ld + gc]) = make_float2(s0, s1);
                } else if (EPI == 3) {
                    v0 += bias1[gc]; v1 += bias1[gc+1];
                    int g = gr * H_ + gc;
                    float2 tv = *reinterpret_cast<const float2*>(&tbuf[g]);
                    float2 sv = *reinterpret_cast<const float2*>(&sgbuf[(size_t)gr * sg_ld + gc]);
                    float t0 = tv.x + v0 * sv.x, t1 = tv.y + v1 * sv.y;
                    *reinterpret_cast<float2*>(&tbuf[g]) = make_float2(t0, t1);
                    float z0 = RELUF ? fmaxf(t0, 0.f) : t0;
                    float z1 = RELUF ? fmaxf(t1, 0.f) : t1;
                    __nv_bfloat162 hv;
                    hv.x = __float2bfloat16(z0);
                    hv.y = __float2bfloat16(z1);
                    *reinterpret_cast<__nv_bfloat162*>(&outX[g]) = hv;
                }
            }
        }
}

// ---------------- product over features (same double shfl-tree order) ----------------
__global__ void prod_kernel(const float* __restrict__ cdf, float* __restrict__ out) {
    int tid = threadIdx.x;
    int r = tid >> 6, f = tid & 63;
    int b = blockIdx.x * 4 + r;
    double vv = (double)cdf[(size_t)b * F_ + f];
    #pragma unroll
    for (int o = 16; o > 0; o >>= 1)
        vv *= __shfl_xor_sync(0xffffffffu, vv, o);
    __shared__ double sred[8];
    int w = tid >> 5;
    if ((tid & 31) == 0) sred[w] = vv;
    __syncthreads();
    if (f == 0) out[b] = (float)(sred[2*r] * sred[2*r + 1]);
}

// ---------------- launch ----------------
extern "C" void kernel_launch(void* const* d_in, const int* in_sizes, int n_in,
                              void* d_out, int out_size) {
    const float* pred  = (const float*)d_in[0];
    const float* ctx   = (const float*)d_in[1];
    const float* W_in  = (const float*)d_in[2];
    const float* b_in  = (const float*)d_in[3];
    const float* Wc_in = (const float*)d_in[4];
    const float* bc_in = (const float*)d_in[5];
    const float* Wb1   = (const float*)d_in[6];
    const float* bb1   = (const float*)d_in[7];
    const float* Wb2   = (const float*)d_in[8];
    const float* bb2   = (const float*)d_in[9];
    const float* Wcb   = (const float*)d_in[10];
    const float* bcb   = (const float*)d_in[11];
    const float* W_out = (const float*)d_in[12];
    const float* b_out = (const float*)d_in[13];
    float* out = (float*)d_out;

    const int SM_BN128 = NSTAGE * (128 + 128) * ROWB;   // 61440; x2 = 122880
    const int SM_BN96  = NSTAGE * (128 + 96) * ROWB;    // 53760
    const int SM_SPL   = 128 * 98 * 4;                  // 50176 <= 53760
    const int SM_OUT   = (SM_BN96 > SM_SPL) ? SM_BN96 : SM_SPL;   // 53760; x2 = 107520

    cudaFuncSetAttribute(gemm_bf1<0,false,0,128,2>, cudaFuncAttributeMaxDynamicSharedMemorySize, SM_BN128);
    cudaFuncSetAttribute(gemm_bf1<2,false,0,128,2>, cudaFuncAttributeMaxDynamicSharedMemorySize, SM_BN128);
    cudaFuncSetAttribute(gemm_bf1<1,false,1,128,2>, cudaFuncAttributeMaxDynamicSharedMemorySize, SM_BN128);
    cudaFuncSetAttribute(gemm_bf1<3,true ,1,128,2>, cudaFuncAttributeMaxDynamicSharedMemorySize, SM_BN128);
    cudaFuncSetAttribute(gemm_bf1<3,false,1,128,2>, cudaFuncAttributeMaxDynamicSharedMemorySize, SM_BN128);
    cudaFuncSetAttribute(gemm_bf1<5,false,2,96,2>,  cudaFuncAttributeMaxDynamicSharedMemorySize, SM_OUT);

    __nv_bfloat16 *A, *X, *Y, *Wc, *Wh, *Wb, *Wo;
    float *t, *sg, *cdfb, *pb;
    cudaGetSymbolAddress((void**)&A, g_A);
    cudaGetSymbolAddress((void**)&X, g_X);
    cudaGetSymbolAddress((void**)&Y, g_Y);
    cudaGetSymbolAddress((void**)&Wc, g_Wcat);
    cudaGetSymbolAddress((void**)&Wh, g_Whh);
    cudaGetSymbolAddress((void**)&Wb, g_Wcb);
    cudaGetSymbolAddress((void**)&Wo, g_Wout);
    cudaGetSymbolAddress((void**)&t, g_t);
    cudaGetSymbolAddress((void**)&sg, g_sg);
    cudaGetSymbolAddress((void**)&cdfb, g_CDF);
    cudaGetSymbolAddress((void**)&pb, g_pb);

    // 1) preps
    prepA   <<<(B_*KIN + 255) / 256, 256>>>(pred, ctx);
    prepWcat<<<(H_*KIN + 255) / 256, 256>>>(W_in, Wc_in);
    prepWhh <<<(2*NBLK*HH + 255) / 256, 256>>>(Wb1, Wb2);
    prepWcb <<<(NBLK*HH + 255) / 256, 256>>>(Wcb);
    prepWout<<<((int)(((size_t)NOUTP*H_ + 255) / 256)), 256>>>(W_out);
    permB   <<<(10*H_ + 255) / 256, 256>>>(b_in, bc_in, bb1, bb2, bcb);

    // 2) t = [pred|ctx] @ Wcat + biases ; X = bf16(relu(t)); tbuf = t
    {
        dim3 g(H_ / 128, B_ / 128);   // (4, 128)
        gemm_bf1<0,false,0,128,2><<<g, 256, SM_BN128>>>(A, KIN, Wc, KIN,
            pb, 0, t, nullptr, nullptr, nullptr, X);
    }

    // 2b) all 3 gates at once: sg[:, i*512+j] = sigmoid(ctx @ Wcb_i + bcb_i)
    {
        dim3 g(NBLK*H_ / 128, B_ / 128);  // (12, 128)
        gemm_bf1<2,false,0,128,2><<<g, 256, SM_BN128>>>(A + F_, KIN,
            Wb, C_, pb + 7*H_, NBLK*H_, nullptr, sg, nullptr, nullptr, nullptr);
    }

    // 3) residual blocks (BM=128/BN=128, occ=2)
    dim3 gHH(H_ / 128, B_ / 128);     // (4, 128)
    for (int i = 0; i < NBLK; i++) {
        gemm_bf1<1,false,1,128,2><<<gHH, 256, SM_BN128>>>(X, H_,
            Wh + (size_t)i*HH, H_,
            pb + (1+i)*H_, 0, nullptr, nullptr, nullptr, nullptr, Y);
        if (i < NBLK - 1)
            gemm_bf1<3,true,1,128,2><<<gHH, 256, SM_BN128>>>(Y, H_,
                Wh + (size_t)(NBLK + i)*HH, H_,
                pb + (4+i)*H_, NBLK*H_, t, sg + i*H_, nullptr, nullptr, X);
        else
            gemm_bf1<3,false,1,128,2><<<gHH, 256, SM_BN128>>>(Y, H_,
                Wh + (size_t)(NBLK + i)*HH, H_,
                pb + (4+i)*H_, NBLK*H_, t, sg + i*H_, nullptr, nullptr, X);
    }

    // 4) out GEMM + fused spline: 1 feature per tile (BN=96), occ=2
    {
        dim3 g(F_, B_ / 128);   // (64, 128)
        gemm_bf1<5,false,2,96,2><<<g, 256, SM_OUT>>>(X, H_, Wo, H_,
            b_out, 0, nullptr, nullptr, pred, cdfb, nullptr);
    }

    // 5) product over features
    prod_kernel<<<B_ / 4, 256>>>(cdfb, out);
}